// round 4
// baseline (speedup 1.0000x reference)
#include <cuda_runtime.h>
#include <cuda_bf16.h>
#include <cstdint>

// ============================================================================
// Compile-time reproduction of np.random.RandomState(0) op sequence
// ============================================================================
struct OpT { int kind; int a; int b; };   // kind: 0=rx 1=ry 2=rz 3=cnot
struct MTc { unsigned mt[624]; int mti; };

constexpr unsigned mt_next(MTc &s) {
    if (s.mti >= 624) {
        for (int i = 0; i < 624; ++i) {
            unsigned y = (s.mt[i] & 0x80000000u) | (s.mt[(i + 1) % 624] & 0x7fffffffu);
            unsigned v = s.mt[(i + 397) % 624] ^ (y >> 1);
            if (y & 1u) v ^= 0x9908b0dfu;
            s.mt[i] = v;
        }
        s.mti = 0;
    }
    unsigned y = s.mt[s.mti++];
    y ^= y >> 11;
    y ^= (y << 7)  & 0x9d2c5680u;
    y ^= (y << 15) & 0xefc60000u;
    y ^= y >> 18;
    return y;
}
constexpr unsigned mt_interval(MTc &s, unsigned maxv) {
    unsigned mask = maxv;
    mask |= mask >> 1; mask |= mask >> 2; mask |= mask >> 4;
    mask |= mask >> 8; mask |= mask >> 16;
    unsigned v = mt_next(s) & mask;
    while (v > maxv) v = mt_next(s) & mask;
    return v;
}
struct Ops { OpT ops[20]; };
constexpr Ops make_ops() {
    Ops o{};
    MTc s{};
    s.mt[0] = 0u;
    for (int i = 1; i < 624; ++i)
        s.mt[i] = 1812433253u * (s.mt[i - 1] ^ (s.mt[i - 1] >> 30)) + (unsigned)i;
    s.mti = 624;
    for (int i = 0; i < 20; ++i) {
        unsigned k = mt_interval(s, 3u);
        if (k == 3u) {
            int perm[8] = {0,1,2,3,4,5,6,7};
            for (int j = 7; j >= 1; --j) {
                unsigned x = mt_interval(s, (unsigned)j);
                int t = perm[j]; perm[j] = perm[x]; perm[x] = t;
            }
            o.ops[i] = OpT{3, perm[0], perm[1]};
        } else {
            unsigned w = mt_interval(s, 7u);
            o.ops[i] = OpT{(int)k, (int)w, 0};
        }
    }
    return o;
}
constexpr Ops OPS = make_ops();

// ============================================================================
// Device globals
// ============================================================================
#define MAX_ROWS 16384
__device__ float g_H[(size_t)MAX_ROWS * 64];

// ============================================================================
// Native u64 f32x2 helpers: all arithmetic stays in 64-bit regs, no per-op
// pack/unpack asm (unpack only at shfl / half-access boundaries).
// ============================================================================
typedef unsigned long long u64;

__device__ __forceinline__ u64 pk2(float x, float y) {
    u64 d; asm("mov.b64 %0, {%1, %2};" : "=l"(d) : "f"(x), "f"(y)); return d;
}
__device__ __forceinline__ float2 up2(u64 v) {
    float2 r; asm("mov.b64 {%0, %1}, %2;" : "=f"(r.x), "=f"(r.y) : "l"(v)); return r;
}
__device__ __forceinline__ u64 fma2(u64 a, u64 b, u64 c) {
    u64 d; asm("fma.rn.f32x2 %0, %1, %2, %3;" : "=l"(d) : "l"(a), "l"(b), "l"(c)); return d;
}
__device__ __forceinline__ u64 mul2(u64 a, u64 b) {
    u64 d; asm("mul.rn.f32x2 %0, %1, %2;" : "=l"(d) : "l"(a), "l"(b)); return d;
}
__device__ __forceinline__ u64 add2(u64 a, u64 b) {
    u64 d; asm("add.rn.f32x2 %0, %1, %2;" : "=l"(d) : "l"(a), "l"(b)); return d;
}
__device__ __forceinline__ u64 sub2(u64 a, u64 b) {
    u64 d; asm("sub.rn.f32x2 %0, %1, %2;" : "=l"(d) : "l"(a), "l"(b)); return d;
}
__device__ __forceinline__ u64 swp(u64 v) {           // swap halves (reg renames)
    float2 t = up2(v); return pk2(t.y, t.x);
}
__device__ __forceinline__ u64 shx(u64 v, int m) {    // shfl_xor both halves
    float2 t = up2(v);
    t.x = __shfl_xor_sync(0xffffffffu, t.x, m);
    t.y = __shfl_xor_sync(0xffffffffu, t.y, m);
    return pk2(t.x, t.y);
}
__device__ __forceinline__ u64 shidx(u64 v, int src) { // shfl idx both halves
    float2 t = up2(v);
    t.x = __shfl_sync(0xffffffffu, t.x, src);
    t.y = __shfl_sync(0xffffffffu, t.y, src);
    return pk2(t.x, t.y);
}

// ============================================================================
// Packed gate application.
// Amp index i = lane*8 + r; r packed as pack k = r>>1, half = r&1 (.x even).
// Bit p of r: p==0 -> half; p in {1,2} -> pack bit p-1; p>=3 -> lane bit p-3.
// ============================================================================
template<int KIND, int A, int B>
__device__ __forceinline__ void gateP(u64 (&RE)[4], u64 (&IM)[4], int lane,
                                      float cc, float ss) {
    constexpr unsigned FULL = 0xffffffffu;
    if constexpr (KIND == 3) {                       // CNOT ctrl A tgt B
        constexpr int pc = 7 - A, pt = 7 - B;
        if constexpr (pc < 3 && pt < 3) {
            if constexpr (pt == 0) {
                constexpr int cb = pc - 1;
                #pragma unroll
                for (int k = 0; k < 4; ++k)
                    if ((k >> cb) & 1) { RE[k] = swp(RE[k]); IM[k] = swp(IM[k]); }
            } else if constexpr (pc == 0) {          // odd halves swap across packs
                constexpr int tb = pt - 1, mm = 1 << tb;
                #pragma unroll
                for (int k = 0; k < 4; ++k)
                    if (!((k >> tb) & 1)) {
                        int q = k + mm;
                        float2 a = up2(RE[k]), b = up2(RE[q]);
                        float t = a.y; a.y = b.y; b.y = t;
                        RE[k] = pk2(a.x, a.y); RE[q] = pk2(b.x, b.y);
                        float2 c2 = up2(IM[k]), d2 = up2(IM[q]);
                        t = c2.y; c2.y = d2.y; d2.y = t;
                        IM[k] = pk2(c2.x, c2.y); IM[q] = pk2(d2.x, d2.y);
                    }
            } else {                                 // pack-level swap
                constexpr int cb = pc - 1, tb = pt - 1, mm = 1 << tb;
                #pragma unroll
                for (int k = 0; k < 4; ++k)
                    if (((k >> cb) & 1) && !((k >> tb) & 1)) {
                        u64 t = RE[k]; RE[k] = RE[k + mm]; RE[k + mm] = t;
                        t = IM[k]; IM[k] = IM[k + mm]; IM[k + mm] = t;
                    }
            }
        } else if constexpr (pc < 3 && pt >= 3) {    // ctrl reg, tgt lane
            constexpr int ml = 1 << (pt - 3);
            if constexpr (pc == 0) {                 // odd halves shuffle
                #pragma unroll
                for (int k = 0; k < 4; ++k) {
                    float2 a = up2(RE[k]);
                    a.y = __shfl_xor_sync(FULL, a.y, ml);
                    RE[k] = pk2(a.x, a.y);
                    float2 b = up2(IM[k]);
                    b.y = __shfl_xor_sync(FULL, b.y, ml);
                    IM[k] = pk2(b.x, b.y);
                }
            } else {
                constexpr int cb = pc - 1;
                #pragma unroll
                for (int k = 0; k < 4; ++k)
                    if ((k >> cb) & 1) { RE[k] = shx(RE[k], ml); IM[k] = shx(IM[k], ml); }
            }
        } else if constexpr (pc >= 3 && pt < 3) {    // ctrl lane, tgt reg
            bool bc = (lane >> (pc - 3)) & 1;
            if constexpr (pt == 0) {
                #pragma unroll
                for (int k = 0; k < 4; ++k) {
                    u64 v = RE[k]; RE[k] = bc ? swp(v) : v;
                    u64 u = IM[k]; IM[k] = bc ? swp(u) : u;
                }
            } else {
                constexpr int tb = pt - 1, mm = 1 << tb;
                #pragma unroll
                for (int k = 0; k < 4; ++k)
                    if (!((k >> tb) & 1)) {
                        int q = k + mm;
                        u64 a = RE[k], b = RE[q];
                        RE[k] = bc ? b : a; RE[q] = bc ? a : b;
                        u64 c2 = IM[k], d2 = IM[q];
                        IM[k] = bc ? d2 : c2; IM[q] = bc ? c2 : d2;
                    }
            }
        } else {                                     // both lane bits
            int bc = (lane >> (pc - 3)) & 1;
            int src = lane ^ (bc << (pt - 3));
            #pragma unroll
            for (int k = 0; k < 4; ++k) {
                RE[k] = shidx(RE[k], src);
                IM[k] = shidx(IM[k], src);
            }
        }
    } else if constexpr (KIND == 2) {                // RZ
        constexpr int p = 7 - A;
        u64 C = pk2(cc, cc);
        if constexpr (p == 0) {
            u64 SE = pk2(-ss, ss), NSE = pk2(ss, -ss);
            #pragma unroll
            for (int k = 0; k < 4; ++k) {
                u64 r0 = fma2(NSE, IM[k], mul2(C, RE[k]));
                IM[k] = fma2(SE, RE[k], mul2(C, IM[k]));
                RE[k] = r0;
            }
        } else if constexpr (p < 3) {
            constexpr int kb = p - 1;
            u64 SP = pk2(ss, ss), SN = pk2(-ss, -ss);
            #pragma unroll
            for (int k = 0; k < 4; ++k) {
                u64 SE  = ((k >> kb) & 1) ? SP : SN;
                u64 NSE = ((k >> kb) & 1) ? SN : SP;
                u64 r0 = fma2(NSE, IM[k], mul2(C, RE[k]));
                IM[k] = fma2(SE, RE[k], mul2(C, IM[k]));
                RE[k] = r0;
            }
        } else {
            float se = ((lane >> (p - 3)) & 1) ? ss : -ss;
            u64 SE = pk2(se, se), NSE = pk2(-se, -se);
            #pragma unroll
            for (int k = 0; k < 4; ++k) {
                u64 r0 = fma2(NSE, IM[k], mul2(C, RE[k]));
                IM[k] = fma2(SE, RE[k], mul2(C, IM[k]));
                RE[k] = r0;
            }
        }
    } else if constexpr (KIND == 0) {                // RX
        constexpr int p = 7 - A;
        u64 C = pk2(cc, cc), S = pk2(ss, ss), NS = pk2(-ss, -ss);
        if constexpr (p == 0) {
            #pragma unroll
            for (int k = 0; k < 4; ++k) {
                u64 rk = RE[k], ik = IM[k];
                RE[k] = fma2(S,  swp(ik), mul2(C, rk));
                IM[k] = fma2(NS, swp(rk), mul2(C, ik));
            }
        } else if constexpr (p < 3) {
            constexpr int kb = p - 1, mm = 1 << kb;
            #pragma unroll
            for (int k = 0; k < 4; ++k)
                if (!((k >> kb) & 1)) {
                    int q = k + mm;
                    u64 rk = RE[k], ik = IM[k], rq = RE[q], iq = IM[q];
                    RE[k] = fma2(S,  iq, mul2(C, rk));
                    IM[k] = fma2(NS, rq, mul2(C, ik));
                    RE[q] = fma2(S,  ik, mul2(C, rq));
                    IM[q] = fma2(NS, rk, mul2(C, iq));
                }
        } else {
            constexpr int m = 1 << (p - 3);
            #pragma unroll
            for (int k = 0; k < 4; ++k) {
                u64 pr = shx(RE[k], m), pi = shx(IM[k], m);
                RE[k] = fma2(S,  pi, mul2(C, RE[k]));
                IM[k] = fma2(NS, pr, mul2(C, IM[k]));
            }
        }
    } else {                                         // RY
        constexpr int p = 7 - A;
        u64 C = pk2(cc, cc);
        if constexpr (p == 0) {
            u64 MS = pk2(-ss, ss);
            #pragma unroll
            for (int k = 0; k < 4; ++k) {
                RE[k] = fma2(MS, swp(RE[k]), mul2(C, RE[k]));
                IM[k] = fma2(MS, swp(IM[k]), mul2(C, IM[k]));
            }
        } else if constexpr (p < 3) {
            constexpr int kb = p - 1, mm = 1 << kb;
            u64 S = pk2(ss, ss), NS = pk2(-ss, -ss);
            #pragma unroll
            for (int k = 0; k < 4; ++k)
                if (!((k >> kb) & 1)) {
                    int q = k + mm;
                    u64 rk = RE[k], rq = RE[q];
                    RE[k] = fma2(NS, rq, mul2(C, rk));
                    RE[q] = fma2(S,  rk, mul2(C, rq));
                    u64 ik = IM[k], iq = IM[q];
                    IM[k] = fma2(NS, iq, mul2(C, ik));
                    IM[q] = fma2(S,  ik, mul2(C, iq));
                }
        } else {
            constexpr int m = 1 << (p - 3);
            float sg = ((lane >> (p - 3)) & 1) ? ss : -ss;
            u64 SG = pk2(sg, sg);
            #pragma unroll
            for (int k = 0; k < 4; ++k) {
                u64 pr = shx(RE[k], m), pi = shx(IM[k], m);
                RE[k] = fma2(SG, pr, mul2(C, RE[k]));
                IM[k] = fma2(SG, pi, mul2(C, IM[k]));
            }
        }
    }
}

template<int I>
__device__ __forceinline__ void apply_opP(u64 (&RE)[4], u64 (&IM)[4], int lane,
                                          const float* cs) {
    gateP<OPS.ops[I].kind, OPS.ops[I].a, OPS.ops[I].b>(RE, IM, lane, cs[2 * I], cs[2 * I + 1]);
}

// ============================================================================
// Kernel 1: warp-per-row statevector sim (native u64 f32x2) + layer 1 -> g_H
// ============================================================================
__global__ __launch_bounds__(256)
void sim_kernel(const float* __restrict__ x, const float* __restrict__ W1,
                const float* __restrict__ b1,
                const float* __restrict__ rp, const float* __restrict__ ryt,
                int rows) {
    constexpr unsigned FULL = 0xffffffffu;
    __shared__ float cs[56];
    {
        int t = threadIdx.x;
        if (t < 20) {
            float sv, cv; sincosf(__ldg(rp + t) * 0.5f, &sv, &cv);
            cs[2 * t] = cv; cs[2 * t + 1] = sv;
        } else if (t < 28) {
            int w = t - 20;
            float sv, cv; sincosf(__ldg(ryt + w) * 0.5f, &sv, &cv);
            cs[40 + 2 * w] = cv; cs[41 + 2 * w] = sv;
        }
    }
    __syncthreads();

    int gw   = (int)((blockIdx.x * blockDim.x + threadIdx.x) >> 5);
    int lane = threadIdx.x & 31;
    if (gw >= rows) return;

    // distributed sincos: lane w<8 computes wire w, broadcast via shfl
    float myc = 1.0f, mys = 0.0f;
    if (lane < 8) {
        float v = __ldg(x + (size_t)gw * 512 + lane) * 0.5f;
        __sincosf(v, &mys, &myc);
    }
    float c[8], s[8];
    #pragma unroll
    for (int w = 0; w < 8; ++w) {
        c[w] = __shfl_sync(FULL, myc, w);
        s[w] = __shfl_sync(FULL, mys, w);
    }

    // product-state init
    float lf = 1.0f;
    #pragma unroll
    for (int w = 0; w < 5; ++w) lf *= ((lane >> (4 - w)) & 1) ? s[w] : c[w];
    u64 RE[4], IM[4];
    u64 CS7 = pk2(c[7], s[7]);
    #pragma unroll
    for (int k = 0; k < 4; ++k) {
        float t = lf * ((k & 2) ? s[5] : c[5]) * ((k & 1) ? s[6] : c[6]);
        RE[k] = mul2(pk2(t, t), CS7);
        IM[k] = 0ull;
    }

    apply_opP<0>(RE, IM, lane, cs);   apply_opP<1>(RE, IM, lane, cs);
    apply_opP<2>(RE, IM, lane, cs);   apply_opP<3>(RE, IM, lane, cs);
    apply_opP<4>(RE, IM, lane, cs);   apply_opP<5>(RE, IM, lane, cs);
    apply_opP<6>(RE, IM, lane, cs);   apply_opP<7>(RE, IM, lane, cs);
    apply_opP<8>(RE, IM, lane, cs);   apply_opP<9>(RE, IM, lane, cs);
    apply_opP<10>(RE, IM, lane, cs);  apply_opP<11>(RE, IM, lane, cs);
    apply_opP<12>(RE, IM, lane, cs);  apply_opP<13>(RE, IM, lane, cs);
    apply_opP<14>(RE, IM, lane, cs);  apply_opP<15>(RE, IM, lane, cs);
    apply_opP<16>(RE, IM, lane, cs);  apply_opP<17>(RE, IM, lane, cs);
    apply_opP<18>(RE, IM, lane, cs);  apply_opP<19>(RE, IM, lane, cs);

    gateP<1, 0, 0>(RE, IM, lane, cs[40], cs[41]);
    gateP<1, 1, 0>(RE, IM, lane, cs[42], cs[43]);
    gateP<1, 2, 0>(RE, IM, lane, cs[44], cs[45]);
    gateP<1, 3, 0>(RE, IM, lane, cs[46], cs[47]);
    gateP<1, 4, 0>(RE, IM, lane, cs[48], cs[49]);
    gateP<1, 5, 0>(RE, IM, lane, cs[50], cs[51]);
    gateP<1, 6, 0>(RE, IM, lane, cs[52], cs[53]);
    gateP<1, 7, 0>(RE, IM, lane, cs[54], cs[55]);

    // probabilities (packed)
    u64 P[4];
    #pragma unroll
    for (int k = 0; k < 4; ++k)
        P[k] = fma2(RE[k], RE[k], mul2(IM[k], IM[k]));

    u64 S01 = add2(P[0], P[1]);
    u64 S23 = add2(P[2], P[3]);
    u64 SAu = add2(S01, S23);
    float2 SA = up2(SAu);
    float ptot = SA.x + SA.y;
    float e7   = SA.x - SA.y;                           // r bit0
    float2 s01 = up2(S01), s23 = up2(S23);
    float e5   = (s01.x + s01.y) - (s23.x + s23.y);     // pack bit1
    float2 d01 = up2(sub2(P[0], P[1]));
    float2 d23 = up2(sub2(P[2], P[3]));
    float e6   = (d01.x + d01.y) + (d23.x + d23.y);     // pack bit0

    u64 EA = pk2(((lane >> 4) & 1) ? -ptot : ptot,
                 ((lane >> 3) & 1) ? -ptot : ptot);
    u64 EB = pk2(((lane >> 2) & 1) ? -ptot : ptot,
                 ((lane >> 1) & 1) ? -ptot : ptot);
    u64 EC = pk2(((lane >> 0) & 1) ? -ptot : ptot, e5);
    u64 ED = pk2(e6, e7);

    #pragma unroll
    for (int off = 16; off > 0; off >>= 1) {
        EA = add2(EA, shx(EA, off));
        EB = add2(EB, shx(EB, off));
        EC = add2(EC, shx(EC, off));
        ED = add2(ED, shx(ED, off));
    }
    float2 ea = up2(EA), eb = up2(EB), ec = up2(EC), ed = up2(ED);
    float ev[8] = {ea.x, ea.y, eb.x, eb.y, ec.x, ec.y, ed.x, ed.y};

    // layer 1: h = relu(ev @ W1^T + b1)
    const float4* w1a = (const float4*)(W1 + (size_t)lane * 8);
    const float4* w1b = (const float4*)(W1 + (size_t)(lane + 32) * 8);
    float4 a0 = __ldg(w1a), a1 = __ldg(w1a + 1);
    float4 v0 = __ldg(w1b), v1 = __ldg(w1b + 1);
    float h0 = __ldg(b1 + lane);
    float h1 = __ldg(b1 + lane + 32);
    h0 = fmaf(a0.x, ev[0], h0); h0 = fmaf(a0.y, ev[1], h0);
    h0 = fmaf(a0.z, ev[2], h0); h0 = fmaf(a0.w, ev[3], h0);
    h0 = fmaf(a1.x, ev[4], h0); h0 = fmaf(a1.y, ev[5], h0);
    h0 = fmaf(a1.z, ev[6], h0); h0 = fmaf(a1.w, ev[7], h0);
    h1 = fmaf(v0.x, ev[0], h1); h1 = fmaf(v0.y, ev[1], h1);
    h1 = fmaf(v0.z, ev[2], h1); h1 = fmaf(v0.w, ev[3], h1);
    h1 = fmaf(v1.x, ev[4], h1); h1 = fmaf(v1.y, ev[5], h1);
    h1 = fmaf(v1.z, ev[6], h1); h1 = fmaf(v1.w, ev[7], h1);
    h0 = fmaxf(h0, 0.0f);
    h1 = fmaxf(h1, 0.0f);
    g_H[(size_t)gw * 64 + lane]      = h0;
    g_H[(size_t)gw * 64 + 32 + lane] = h1;
}

// ============================================================================
// Kernel 2: out = H @ W2^T + b2  (M=16384, N=512, K=64) tf32 mma.m16n8k8
// M-tile 128, N-tile 64 -> smem 55KB -> 4 blocks/SM; grid 1024 blocks.
// Fragment-order smem: uint2(A[row][k], A[row][k+4]) at [row*ST2 + kk*4 + tg]
// ============================================================================
#define ST2 36

__device__ __forceinline__ uint32_t f2tf32(float f) {
    uint32_t r;
    asm("cvt.rna.tf32.f32 %0, %1;" : "=r"(r) : "f"(f));
    return r;
}

__global__ __launch_bounds__(256)
void gemm_kernel(const float* __restrict__ W2, const float* __restrict__ b2,
                 float* __restrict__ out) {
    extern __shared__ uint2 sm2[];
    uint2* As = sm2;                 // 128 * ST2
    uint2* Bs = sm2 + 128 * ST2;     //  64 * ST2

    int t  = threadIdx.x;
    int bm = blockIdx.y * 128;
    int bn = blockIdx.x * 64;

    const float4* Hg = (const float4*)(g_H + (size_t)bm * 64);
    const float4* Wg = (const float4*)(W2 + (size_t)bn * 64);
    #pragma unroll
    for (int i = 0; i < 4; ++i) {               // A: 1024 (row,kk) tasks
        int task = i * 256 + t;
        int row = task >> 3, kk = task & 7;
        float4 a0 = __ldg(Hg + row * 16 + kk * 2);
        float4 a1 = __ldg(Hg + row * 16 + kk * 2 + 1);
        uint2* pa = As + row * ST2 + kk * 4;
        pa[0] = make_uint2(f2tf32(a0.x), f2tf32(a1.x));
        pa[1] = make_uint2(f2tf32(a0.y), f2tf32(a1.y));
        pa[2] = make_uint2(f2tf32(a0.z), f2tf32(a1.z));
        pa[3] = make_uint2(f2tf32(a0.w), f2tf32(a1.w));
    }
    #pragma unroll
    for (int i = 0; i < 2; ++i) {               // B: 512 (row,kk) tasks
        int task = i * 256 + t;
        int row = task >> 3, kk = task & 7;
        float4 bb0 = __ldg(Wg + row * 16 + kk * 2);
        float4 bb1 = __ldg(Wg + row * 16 + kk * 2 + 1);
        uint2* pb = Bs + row * ST2 + kk * 4;
        pb[0] = make_uint2(f2tf32(bb0.x), f2tf32(bb1.x));
        pb[1] = make_uint2(f2tf32(bb0.y), f2tf32(bb1.y));
        pb[2] = make_uint2(f2tf32(bb0.z), f2tf32(bb1.z));
        pb[3] = make_uint2(f2tf32(bb0.w), f2tf32(bb1.w));
    }
    __syncthreads();

    int lane = t & 31, wid = t >> 5;
    int wm = (wid >> 1) * 32;        // 4 warps in M: 0,32,64,96
    int wn = (wid & 1) * 32;         // 2 warps in N: 0,32
    int g  = lane >> 2;
    int tg = lane & 3;

    float acc[2][4][4];
    #pragma unroll
    for (int f = 0; f < 2; ++f)
        #pragma unroll
        for (int j = 0; j < 4; ++j)
            #pragma unroll
            for (int q = 0; q < 4; ++q) acc[f][j][q] = 0.0f;

    #pragma unroll
    for (int kk = 0; kk < 8; ++kk) {
        int kb = kk * 4 + tg;
        uint2 va0 = As[(wm + g) * ST2 + kb];
        uint2 va1 = As[(wm + g + 8) * ST2 + kb];
        uint2 va2 = As[(wm + g + 16) * ST2 + kb];
        uint2 va3 = As[(wm + g + 24) * ST2 + kb];
        uint32_t a[2][4] = {
            { va0.x, va1.x, va0.y, va1.y },
            { va2.x, va3.x, va2.y, va3.y }
        };
        uint2 wb[4];
        #pragma unroll
        for (int j = 0; j < 4; ++j)
            wb[j] = Bs[(wn + j * 8 + g) * ST2 + kb];

        #pragma unroll
        for (int f = 0; f < 2; ++f)
            #pragma unroll
            for (int j = 0; j < 4; ++j)
                asm volatile(
                    "mma.sync.aligned.m16n8k8.row.col.f32.tf32.tf32.f32 "
                    "{%0,%1,%2,%3}, {%4,%5,%6,%7}, {%8,%9}, {%0,%1,%2,%3};"
                    : "+f"(acc[f][j][0]), "+f"(acc[f][j][1]),
                      "+f"(acc[f][j][2]), "+f"(acc[f][j][3])
                    : "r"(a[f][0]), "r"(a[f][1]), "r"(a[f][2]), "r"(a[f][3]),
                      "r"(wb[j].x), "r"(wb[j].y));
    }

    #pragma unroll
    for (int j = 0; j < 4; ++j) {
        int col = bn + wn + j * 8 + tg * 2;
        float2 bias = __ldg((const float2*)(b2 + col));
        #pragma unroll
        for (int f = 0; f < 2; ++f) {
            int row = bm + wm + f * 16 + g;
            float2 o0 = { acc[f][j][0] + bias.x, acc[f][j][1] + bias.y };
            float2 o1 = { acc[f][j][2] + bias.x, acc[f][j][3] + bias.y };
            *(float2*)(out + (size_t)row * 512 + col)       = o0;
            *(float2*)(out + (size_t)(row + 8) * 512 + col) = o1;
        }
    }
}

// ============================================================================
// Launch
// ============================================================================
extern "C" void kernel_launch(void* const* d_in, const int* in_sizes, int n_in,
                              void* d_out, int out_size) {
    const float* x   = (const float*)d_in[0];
    const float* ryt = (const float*)d_in[1];
    const float* rp  = (const float*)d_in[2];
    const float* W1  = (const float*)d_in[3];
    const float* b1  = (const float*)d_in[4];
    const float* W2  = (const float*)d_in[5];
    const float* b2  = (const float*)d_in[6];
    float* out = (float*)d_out;

    int rows = in_sizes[0] / 512;            // B*S = 16384

    int simBlocks = (rows + 7) / 8;
    sim_kernel<<<simBlocks, 256>>>(x, W1, b1, rp, ryt, rows);

    const int gemm_smem = (128 + 64) * ST2 * (int)sizeof(uint2);   // 55.3 KB
    cudaFuncSetAttribute(gemm_kernel, cudaFuncAttributeMaxDynamicSharedMemorySize, gemm_smem);
    dim3 ggrid(512 / 64, rows / 128);
    gemm_kernel<<<ggrid, 256, gemm_smem>>>(W2, b2, out);
}

// round 5
// speedup vs baseline: 1.2388x; 1.2388x over previous
#include <cuda_runtime.h>
#include <cuda_bf16.h>
#include <cstdint>

// ============================================================================
// Compile-time reproduction of np.random.RandomState(0) op sequence
// ============================================================================
struct OpT { int kind; int a; int b; };   // kind: 0=rx 1=ry 2=rz 3=cnot
struct MTc { unsigned mt[624]; int mti; };

constexpr unsigned mt_next(MTc &s) {
    if (s.mti >= 624) {
        for (int i = 0; i < 624; ++i) {
            unsigned y = (s.mt[i] & 0x80000000u) | (s.mt[(i + 1) % 624] & 0x7fffffffu);
            unsigned v = s.mt[(i + 397) % 624] ^ (y >> 1);
            if (y & 1u) v ^= 0x9908b0dfu;
            s.mt[i] = v;
        }
        s.mti = 0;
    }
    unsigned y = s.mt[s.mti++];
    y ^= y >> 11;
    y ^= (y << 7)  & 0x9d2c5680u;
    y ^= (y << 15) & 0xefc60000u;
    y ^= y >> 18;
    return y;
}
constexpr unsigned mt_interval(MTc &s, unsigned maxv) {
    unsigned mask = maxv;
    mask |= mask >> 1; mask |= mask >> 2; mask |= mask >> 4;
    mask |= mask >> 8; mask |= mask >> 16;
    unsigned v = mt_next(s) & mask;
    while (v > maxv) v = mt_next(s) & mask;
    return v;
}
struct Ops { OpT ops[20]; };
constexpr Ops make_ops() {
    Ops o{};
    MTc s{};
    s.mt[0] = 0u;
    for (int i = 1; i < 624; ++i)
        s.mt[i] = 1812433253u * (s.mt[i - 1] ^ (s.mt[i - 1] >> 30)) + (unsigned)i;
    s.mti = 624;
    for (int i = 0; i < 20; ++i) {
        unsigned k = mt_interval(s, 3u);
        if (k == 3u) {
            int perm[8] = {0,1,2,3,4,5,6,7};
            for (int j = 7; j >= 1; --j) {
                unsigned x = mt_interval(s, (unsigned)j);
                int t = perm[j]; perm[j] = perm[x]; perm[x] = t;
            }
            o.ops[i] = OpT{3, perm[0], perm[1]};
        } else {
            unsigned w = mt_interval(s, 7u);
            o.ops[i] = OpT{(int)k, (int)w, 0};
        }
    }
    return o;
}
constexpr Ops OPS = make_ops();

// ============================================================================
// Packed fp32x2 helpers (R3 float2-wrapper version — measured best)
// ============================================================================
__device__ __forceinline__ float2 f2mul(float2 a, float2 b) {
    float2 d;
    asm("{\n\t"
        ".reg .b64 ra, rb, rd;\n\t"
        "mov.b64 ra, {%2, %3};\n\t"
        "mov.b64 rb, {%4, %5};\n\t"
        "mul.rn.f32x2 rd, ra, rb;\n\t"
        "mov.b64 {%0, %1}, rd;\n\t"
        "}"
        : "=f"(d.x), "=f"(d.y)
        : "f"(a.x), "f"(a.y), "f"(b.x), "f"(b.y));
    return d;
}
__device__ __forceinline__ float2 f2fma(float2 a, float2 b, float2 c) {
    float2 d;
    asm("{\n\t"
        ".reg .b64 ra, rb, rc, rd;\n\t"
        "mov.b64 ra, {%2, %3};\n\t"
        "mov.b64 rb, {%4, %5};\n\t"
        "mov.b64 rc, {%6, %7};\n\t"
        "fma.rn.f32x2 rd, ra, rb, rc;\n\t"
        "mov.b64 {%0, %1}, rd;\n\t"
        "}"
        : "=f"(d.x), "=f"(d.y)
        : "f"(a.x), "f"(a.y), "f"(b.x), "f"(b.y), "f"(c.x), "f"(c.y));
    return d;
}
__device__ __forceinline__ float2 f2add(float2 a, float2 b) {
    float2 d;
    asm("{\n\t"
        ".reg .b64 ra, rb, rd;\n\t"
        "mov.b64 ra, {%2, %3};\n\t"
        "mov.b64 rb, {%4, %5};\n\t"
        "add.rn.f32x2 rd, ra, rb;\n\t"
        "mov.b64 {%0, %1}, rd;\n\t"
        "}"
        : "=f"(d.x), "=f"(d.y)
        : "f"(a.x), "f"(a.y), "f"(b.x), "f"(b.y));
    return d;
}
__device__ __forceinline__ float2 shfl_xor2(float2 v, int m) {
    v.x = __shfl_xor_sync(0xffffffffu, v.x, m);
    v.y = __shfl_xor_sync(0xffffffffu, v.y, m);
    return v;
}

// ============================================================================
// Packed gate application (R3 version, measured best).
// Amp index i = lane*8 + r; pack k = r>>1, half = r&1 (.x even).
// Bit p of r: p==0 -> half; p in {1,2} -> pack bit p-1; p>=3 -> lane bit p-3.
// ============================================================================
template<int KIND, int A, int B>
__device__ __forceinline__ void gateP(float2 (&RE)[4], float2 (&IM)[4], int lane,
                                      float cc, float ss) {
    constexpr unsigned FULL = 0xffffffffu;
    if constexpr (KIND == 3) {                       // CNOT ctrl A tgt B
        constexpr int pc = 7 - A, pt = 7 - B;
        if constexpr (pc < 3 && pt < 3) {
            if constexpr (pt == 0) {
                constexpr int cb = pc - 1;
                #pragma unroll
                for (int k = 0; k < 4; ++k)
                    if ((k >> cb) & 1) {
                        RE[k] = make_float2(RE[k].y, RE[k].x);
                        IM[k] = make_float2(IM[k].y, IM[k].x);
                    }
            } else if constexpr (pc == 0) {
                constexpr int tb = pt - 1, mm = 1 << tb;
                #pragma unroll
                for (int k = 0; k < 4; ++k)
                    if (!((k >> tb) & 1)) {
                        int q = k + mm;
                        float t = RE[k].y; RE[k].y = RE[q].y; RE[q].y = t;
                        t = IM[k].y; IM[k].y = IM[q].y; IM[q].y = t;
                    }
            } else {
                constexpr int cb = pc - 1, tb = pt - 1, mm = 1 << tb;
                #pragma unroll
                for (int k = 0; k < 4; ++k)
                    if (((k >> cb) & 1) && !((k >> tb) & 1)) {
                        float2 t = RE[k]; RE[k] = RE[k + mm]; RE[k + mm] = t;
                        t = IM[k]; IM[k] = IM[k + mm]; IM[k + mm] = t;
                    }
            }
        } else if constexpr (pc < 3 && pt >= 3) {
            constexpr int ml = 1 << (pt - 3);
            if constexpr (pc == 0) {
                #pragma unroll
                for (int k = 0; k < 4; ++k) {
                    RE[k].y = __shfl_xor_sync(FULL, RE[k].y, ml);
                    IM[k].y = __shfl_xor_sync(FULL, IM[k].y, ml);
                }
            } else {
                constexpr int cb = pc - 1;
                #pragma unroll
                for (int k = 0; k < 4; ++k)
                    if ((k >> cb) & 1) {
                        RE[k] = shfl_xor2(RE[k], ml);
                        IM[k] = shfl_xor2(IM[k], ml);
                    }
            }
        } else if constexpr (pc >= 3 && pt < 3) {
            bool bc = (lane >> (pc - 3)) & 1;
            if constexpr (pt == 0) {
                #pragma unroll
                for (int k = 0; k < 4; ++k) {
                    float2 v = RE[k];
                    RE[k] = bc ? make_float2(v.y, v.x) : v;
                    float2 u = IM[k];
                    IM[k] = bc ? make_float2(u.y, u.x) : u;
                }
            } else {
                constexpr int tb = pt - 1, mm = 1 << tb;
                #pragma unroll
                for (int k = 0; k < 4; ++k)
                    if (!((k >> tb) & 1)) {
                        int q = k + mm;
                        float2 a = RE[k], b2v = RE[q];
                        RE[k] = bc ? b2v : a; RE[q] = bc ? a : b2v;
                        float2 c2 = IM[k], d2 = IM[q];
                        IM[k] = bc ? d2 : c2; IM[q] = bc ? c2 : d2;
                    }
            }
        } else {
            int bc = (lane >> (pc - 3)) & 1;
            int src = lane ^ (bc << (pt - 3));
            #pragma unroll
            for (int k = 0; k < 4; ++k) {
                RE[k].x = __shfl_sync(FULL, RE[k].x, src);
                RE[k].y = __shfl_sync(FULL, RE[k].y, src);
                IM[k].x = __shfl_sync(FULL, IM[k].x, src);
                IM[k].y = __shfl_sync(FULL, IM[k].y, src);
            }
        }
    } else if constexpr (KIND == 2) {                // RZ
        constexpr int p = 7 - A;
        float2 C = make_float2(cc, cc);
        if constexpr (p == 0) {
            float2 SE  = make_float2(-ss,  ss);
            float2 NSE = make_float2( ss, -ss);
            #pragma unroll
            for (int k = 0; k < 4; ++k) {
                float2 r0 = f2fma(NSE, IM[k], f2mul(C, RE[k]));
                IM[k] = f2fma(SE, RE[k], f2mul(C, IM[k]));
                RE[k] = r0;
            }
        } else if constexpr (p < 3) {
            constexpr int kb = p - 1;
            float2 SP = make_float2( ss,  ss);
            float2 SN = make_float2(-ss, -ss);
            #pragma unroll
            for (int k = 0; k < 4; ++k) {
                float2 SE  = ((k >> kb) & 1) ? SP : SN;
                float2 NSE = ((k >> kb) & 1) ? SN : SP;
                float2 r0 = f2fma(NSE, IM[k], f2mul(C, RE[k]));
                IM[k] = f2fma(SE, RE[k], f2mul(C, IM[k]));
                RE[k] = r0;
            }
        } else {
            float se = ((lane >> (p - 3)) & 1) ? ss : -ss;
            float2 SE  = make_float2( se,  se);
            float2 NSE = make_float2(-se, -se);
            #pragma unroll
            for (int k = 0; k < 4; ++k) {
                float2 r0 = f2fma(NSE, IM[k], f2mul(C, RE[k]));
                IM[k] = f2fma(SE, RE[k], f2mul(C, IM[k]));
                RE[k] = r0;
            }
        }
    } else if constexpr (KIND == 0) {                // RX
        constexpr int p = 7 - A;
        float2 C  = make_float2(cc, cc);
        float2 S  = make_float2( ss,  ss);
        float2 NS = make_float2(-ss, -ss);
        if constexpr (p == 0) {
            #pragma unroll
            for (int k = 0; k < 4; ++k) {
                float2 isw = make_float2(IM[k].y, IM[k].x);
                float2 rsw = make_float2(RE[k].y, RE[k].x);
                RE[k] = f2fma(S,  isw, f2mul(C, RE[k]));
                IM[k] = f2fma(NS, rsw, f2mul(C, IM[k]));
            }
        } else if constexpr (p < 3) {
            constexpr int kb = p - 1, mm = 1 << kb;
            #pragma unroll
            for (int k = 0; k < 4; ++k)
                if (!((k >> kb) & 1)) {
                    int q = k + mm;
                    float2 rk = RE[k], ik = IM[k], rq = RE[q], iq = IM[q];
                    RE[k] = f2fma(S,  iq, f2mul(C, rk));
                    IM[k] = f2fma(NS, rq, f2mul(C, ik));
                    RE[q] = f2fma(S,  ik, f2mul(C, rq));
                    IM[q] = f2fma(NS, rk, f2mul(C, iq));
                }
        } else {
            constexpr int m = 1 << (p - 3);
            #pragma unroll
            for (int k = 0; k < 4; ++k) {
                float2 pr = shfl_xor2(RE[k], m);
                float2 pi = shfl_xor2(IM[k], m);
                RE[k] = f2fma(S,  pi, f2mul(C, RE[k]));
                IM[k] = f2fma(NS, pr, f2mul(C, IM[k]));
            }
        }
    } else {                                         // RY
        constexpr int p = 7 - A;
        float2 C = make_float2(cc, cc);
        if constexpr (p == 0) {
            float2 MS = make_float2(-ss, ss);
            #pragma unroll
            for (int k = 0; k < 4; ++k) {
                float2 rsw = make_float2(RE[k].y, RE[k].x);
                float2 isw = make_float2(IM[k].y, IM[k].x);
                RE[k] = f2fma(MS, rsw, f2mul(C, RE[k]));
                IM[k] = f2fma(MS, isw, f2mul(C, IM[k]));
            }
        } else if constexpr (p < 3) {
            constexpr int kb = p - 1, mm = 1 << kb;
            float2 S  = make_float2( ss,  ss);
            float2 NS = make_float2(-ss, -ss);
            #pragma unroll
            for (int k = 0; k < 4; ++k)
                if (!((k >> kb) & 1)) {
                    int q = k + mm;
                    float2 rk = RE[k], rq = RE[q];
                    RE[k] = f2fma(NS, rq, f2mul(C, rk));
                    RE[q] = f2fma(S,  rk, f2mul(C, rq));
                    float2 ik = IM[k], iq = IM[q];
                    IM[k] = f2fma(NS, iq, f2mul(C, ik));
                    IM[q] = f2fma(S,  ik, f2mul(C, iq));
                }
        } else {
            constexpr int m = 1 << (p - 3);
            float sg = ((lane >> (p - 3)) & 1) ? ss : -ss;
            float2 SG = make_float2(sg, sg);
            #pragma unroll
            for (int k = 0; k < 4; ++k) {
                float2 pr = shfl_xor2(RE[k], m);
                float2 pi = shfl_xor2(IM[k], m);
                RE[k] = f2fma(SG, pr, f2mul(C, RE[k]));
                IM[k] = f2fma(SG, pi, f2mul(C, IM[k]));
            }
        }
    }
}

template<int I>
__device__ __forceinline__ void apply_opP(float2 (&RE)[4], float2 (&IM)[4], int lane,
                                          const float* cs) {
    gateP<OPS.ops[I].kind, OPS.ops[I].a, OPS.ops[I].b>(RE, IM, lane, cs[2 * I], cs[2 * I + 1]);
}

// ============================================================================
// Fused kernel: 1 block = 128 rows. 512 threads, 1 block/SM, single wave.
//  Phase 0: coefficients + per-row feature sincos -> smem
//  Phase 1: warp w simulates rows w*8..w*8+7, writes h as tf32 fragments -> As
//  Phase 2: in-block GEMM 128x512 (tf32 mma), 2 halves x 2 N-chunk iterations
// ============================================================================
#define ST2 36

__device__ __forceinline__ uint32_t f2tf32(float f) {
    uint32_t r;
    asm("cvt.rna.tf32.f32 %0, %1;" : "=r"(r) : "f"(f));
    return r;
}

__global__ __launch_bounds__(512, 1)
void fused_kernel(const float* __restrict__ x, const float* __restrict__ W1,
                  const float* __restrict__ b1,
                  const float* __restrict__ rp, const float* __restrict__ ryt,
                  const float* __restrict__ W2, const float* __restrict__ b2,
                  float* __restrict__ out) {
    constexpr unsigned FULL = 0xffffffffu;
    extern __shared__ char smraw[];
    uint2* As = (uint2*)smraw;                       // [128][ST2]  h tile (tf32 frag pairs)
    uint2* Bs = As + 128 * ST2;                      // 2 x [128][ST2] W2 chunks
    float* fs = (float*)(Bs + 2 * 128 * ST2);        // [128][16] feature (c,s) pairs
    float* cs = fs + 128 * 16;                       // [56] gate coefficients

    int t    = threadIdx.x;
    int lane = t & 31;
    int wid  = t >> 5;
    int bm   = blockIdx.x * 128;

    // ---------------- Phase 0: coefficients + feature sincos ----------------
    if (t < 20) {
        float sv, cv; sincosf(__ldg(rp + t) * 0.5f, &sv, &cv);
        cs[2 * t] = cv; cs[2 * t + 1] = sv;
    } else if (t < 28) {
        int w = t - 20;
        float sv, cv; sincosf(__ldg(ryt + w) * 0.5f, &sv, &cv);
        cs[40 + 2 * w] = cv; cs[41 + 2 * w] = sv;
    }
    #pragma unroll
    for (int i = 0; i < 2; ++i) {            // 1024 (row, wire) tasks / 512 threads
        int task = i * 512 + t;
        int row = task >> 3, w = task & 7;
        float v = __ldg(x + (size_t)(bm + row) * 512 + w) * 0.5f;
        float sv, cv; __sincosf(v, &sv, &cv);
        fs[row * 16 + 2 * w]     = cv;
        fs[row * 16 + 2 * w + 1] = sv;
    }
    __syncthreads();

    // ---------------- Phase 1: simulate 8 rows per warp ----------------
    {
        // warp-invariant W1/b1 fragments
        const float4* w1a = (const float4*)(W1 + (size_t)lane * 8);
        const float4* w1b = (const float4*)(W1 + (size_t)(lane + 32) * 8);
        float4 A0 = __ldg(w1a), A1 = __ldg(w1a + 1);
        float4 V0 = __ldg(w1b), V1 = __ldg(w1b + 1);
        float Bb0 = __ldg(b1 + lane), Bb1 = __ldg(b1 + lane + 32);

        for (int r = 0; r < 8; ++r) {
            int row = wid * 8 + r;
            const float4* fp = (const float4*)(fs + row * 16);
            float4 q0 = fp[0], q1 = fp[1], q2 = fp[2], q3 = fp[3];
            float c[8] = {q0.x, q0.z, q1.x, q1.z, q2.x, q2.z, q3.x, q3.z};
            float s[8] = {q0.y, q0.w, q1.y, q1.w, q2.y, q2.w, q3.y, q3.w};

            // product-state init
            float lf = 1.0f;
            #pragma unroll
            for (int w = 0; w < 5; ++w) lf *= ((lane >> (4 - w)) & 1) ? s[w] : c[w];
            float2 RE[4], IM[4];
            float2 CS7 = make_float2(c[7], s[7]);
            #pragma unroll
            for (int k = 0; k < 4; ++k) {
                float tv = lf * ((k & 2) ? s[5] : c[5]) * ((k & 1) ? s[6] : c[6]);
                RE[k] = f2mul(make_float2(tv, tv), CS7);
                IM[k] = make_float2(0.0f, 0.0f);
            }

            apply_opP<0>(RE, IM, lane, cs);   apply_opP<1>(RE, IM, lane, cs);
            apply_opP<2>(RE, IM, lane, cs);   apply_opP<3>(RE, IM, lane, cs);
            apply_opP<4>(RE, IM, lane, cs);   apply_opP<5>(RE, IM, lane, cs);
            apply_opP<6>(RE, IM, lane, cs);   apply_opP<7>(RE, IM, lane, cs);
            apply_opP<8>(RE, IM, lane, cs);   apply_opP<9>(RE, IM, lane, cs);
            apply_opP<10>(RE, IM, lane, cs);  apply_opP<11>(RE, IM, lane, cs);
            apply_opP<12>(RE, IM, lane, cs);  apply_opP<13>(RE, IM, lane, cs);
            apply_opP<14>(RE, IM, lane, cs);  apply_opP<15>(RE, IM, lane, cs);
            apply_opP<16>(RE, IM, lane, cs);  apply_opP<17>(RE, IM, lane, cs);
            apply_opP<18>(RE, IM, lane, cs);  apply_opP<19>(RE, IM, lane, cs);

            gateP<1, 0, 0>(RE, IM, lane, cs[40], cs[41]);
            gateP<1, 1, 0>(RE, IM, lane, cs[42], cs[43]);
            gateP<1, 2, 0>(RE, IM, lane, cs[44], cs[45]);
            gateP<1, 3, 0>(RE, IM, lane, cs[46], cs[47]);
            gateP<1, 4, 0>(RE, IM, lane, cs[48], cs[49]);
            gateP<1, 5, 0>(RE, IM, lane, cs[50], cs[51]);
            gateP<1, 6, 0>(RE, IM, lane, cs[52], cs[53]);
            gateP<1, 7, 0>(RE, IM, lane, cs[54], cs[55]);

            // probabilities (packed)
            float2 P[4];
            #pragma unroll
            for (int k = 0; k < 4; ++k)
                P[k] = f2fma(RE[k], RE[k], f2mul(IM[k], IM[k]));

            float2 S01 = f2add(P[0], P[1]);
            float2 S23 = f2add(P[2], P[3]);
            float2 SA  = f2add(S01, S23);
            float ptot = SA.x + SA.y;
            float e7   = SA.x - SA.y;
            float e5   = (S01.x + S01.y) - (S23.x + S23.y);
            float2 D01 = f2add(P[0], make_float2(-P[1].x, -P[1].y));
            float2 D23 = f2add(P[2], make_float2(-P[3].x, -P[3].y));
            float e6   = (D01.x + D01.y) + (D23.x + D23.y);

            float2 EA = make_float2(((lane >> 4) & 1) ? -ptot : ptot,
                                    ((lane >> 3) & 1) ? -ptot : ptot);
            float2 EB = make_float2(((lane >> 2) & 1) ? -ptot : ptot,
                                    ((lane >> 1) & 1) ? -ptot : ptot);
            float2 EC = make_float2(((lane >> 0) & 1) ? -ptot : ptot, e5);
            float2 ED = make_float2(e6, e7);

            #pragma unroll
            for (int off = 16; off > 0; off >>= 1) {
                EA = f2add(EA, shfl_xor2(EA, off));
                EB = f2add(EB, shfl_xor2(EB, off));
                EC = f2add(EC, shfl_xor2(EC, off));
                ED = f2add(ED, shfl_xor2(ED, off));
            }
            float ev[8] = {EA.x, EA.y, EB.x, EB.y, EC.x, EC.y, ED.x, ED.y};

            // layer 1
            float h0 = Bb0, h1 = Bb1;
            h0 = fmaf(A0.x, ev[0], h0); h0 = fmaf(A0.y, ev[1], h0);
            h0 = fmaf(A0.z, ev[2], h0); h0 = fmaf(A0.w, ev[3], h0);
            h0 = fmaf(A1.x, ev[4], h0); h0 = fmaf(A1.y, ev[5], h0);
            h0 = fmaf(A1.z, ev[6], h0); h0 = fmaf(A1.w, ev[7], h0);
            h1 = fmaf(V0.x, ev[0], h1); h1 = fmaf(V0.y, ev[1], h1);
            h1 = fmaf(V0.z, ev[2], h1); h1 = fmaf(V0.w, ev[3], h1);
            h1 = fmaf(V1.x, ev[4], h1); h1 = fmaf(V1.y, ev[5], h1);
            h1 = fmaf(V1.z, ev[6], h1); h1 = fmaf(V1.w, ev[7], h1);
            h0 = fmaxf(h0, 0.0f);
            h1 = fmaxf(h1, 0.0f);

            // pack to tf32 fragment layout: uint2(h[k], h[k+4])
            float ph0 = __shfl_xor_sync(FULL, h0, 4);
            float ph1 = __shfl_xor_sync(FULL, h1, 4);
            if (!(lane & 4)) {
                int pos = (lane >> 3) * 4 + (lane & 3);
                As[row * ST2 + pos]      = make_uint2(f2tf32(h0), f2tf32(ph0));
                As[row * ST2 + 16 + pos] = make_uint2(f2tf32(h1), f2tf32(ph1));
            }
        }
    }
    __syncthreads();

    // ---------------- Phase 2: in-block GEMM 128 x 512 ----------------
    int half = wid >> 3;           // 0/1 — which N-chunk this warp set works
    int wid8 = wid & 7;
    int wm = (wid8 >> 1) * 32;     // 4 warps in M
    int wn = (wid8 & 1) * 64;      // 2 warps in N (within 128-chunk)
    int g  = lane >> 2;
    int tg = lane & 3;
    int ht = t & 255;              // thread id within half
    uint2* Bh = Bs + half * 128 * ST2;

    #pragma unroll
    for (int it = 0; it < 2; ++it) {
        int chunk = it * 2 + half;           // 0..3
        int bn = chunk * 128;

        // stage W2 chunk (this half's 256 threads)
        const float4* Wg = (const float4*)(W2 + (size_t)bn * 64);
        #pragma unroll
        for (int i = 0; i < 4; ++i) {        // 1024 (row,kk) tasks / 256 threads
            int task = i * 256 + ht;
            int rowN = task >> 3, kk = task & 7;
            float4 b0 = __ldg(Wg + rowN * 16 + kk * 2);
            float4 b1v = __ldg(Wg + rowN * 16 + kk * 2 + 1);
            uint2* pb = Bh + rowN * ST2 + kk * 4;
            pb[0] = make_uint2(f2tf32(b0.x), f2tf32(b1v.x));
            pb[1] = make_uint2(f2tf32(b0.y), f2tf32(b1v.y));
            pb[2] = make_uint2(f2tf32(b0.z), f2tf32(b1v.z));
            pb[3] = make_uint2(f2tf32(b0.w), f2tf32(b1v.w));
        }
        __syncthreads();

        float acc[2][8][4];
        #pragma unroll
        for (int f = 0; f < 2; ++f)
            #pragma unroll
            for (int j = 0; j < 8; ++j)
                #pragma unroll
                for (int q = 0; q < 4; ++q) acc[f][j][q] = 0.0f;

        #pragma unroll
        for (int kk = 0; kk < 8; ++kk) {
            int kb = kk * 4 + tg;
            uint2 va0 = As[(wm + g) * ST2 + kb];
            uint2 va1 = As[(wm + g + 8) * ST2 + kb];
            uint2 va2 = As[(wm + g + 16) * ST2 + kb];
            uint2 va3 = As[(wm + g + 24) * ST2 + kb];
            uint32_t a[2][4] = {
                { va0.x, va1.x, va0.y, va1.y },
                { va2.x, va3.x, va2.y, va3.y }
            };
            uint2 wb[8];
            #pragma unroll
            for (int j = 0; j < 8; ++j)
                wb[j] = Bh[(wn + j * 8 + g) * ST2 + kb];

            #pragma unroll
            for (int f = 0; f < 2; ++f)
                #pragma unroll
                for (int j = 0; j < 8; ++j)
                    asm volatile(
                        "mma.sync.aligned.m16n8k8.row.col.f32.tf32.tf32.f32 "
                        "{%0,%1,%2,%3}, {%4,%5,%6,%7}, {%8,%9}, {%0,%1,%2,%3};"
                        : "+f"(acc[f][j][0]), "+f"(acc[f][j][1]),
                          "+f"(acc[f][j][2]), "+f"(acc[f][j][3])
                        : "r"(a[f][0]), "r"(a[f][1]), "r"(a[f][2]), "r"(a[f][3]),
                          "r"(wb[j].x), "r"(wb[j].y));
        }

        // epilogue
        #pragma unroll
        for (int j = 0; j < 8; ++j) {
            int col = bn + wn + j * 8 + tg * 2;
            float2 bias = __ldg((const float2*)(b2 + col));
            #pragma unroll
            for (int f = 0; f < 2; ++f) {
                int row = bm + wm + f * 16 + g;
                float2 o0 = { acc[f][j][0] + bias.x, acc[f][j][1] + bias.y };
                float2 o1 = { acc[f][j][2] + bias.x, acc[f][j][3] + bias.y };
                *(float2*)(out + (size_t)row * 512 + col)       = o0;
                *(float2*)(out + (size_t)(row + 8) * 512 + col) = o1;
            }
        }
        __syncthreads();
    }
}

// ============================================================================
// Launch
// ============================================================================
extern "C" void kernel_launch(void* const* d_in, const int* in_sizes, int n_in,
                              void* d_out, int out_size) {
    const float* x   = (const float*)d_in[0];
    const float* ryt = (const float*)d_in[1];
    const float* rp  = (const float*)d_in[2];
    const float* W1  = (const float*)d_in[3];
    const float* b1  = (const float*)d_in[4];
    const float* W2  = (const float*)d_in[5];
    const float* b2  = (const float*)d_in[6];
    float* out = (float*)d_out;

    int rows = in_sizes[0] / 512;            // B*S = 16384

    const int smem = 3 * 128 * ST2 * (int)sizeof(uint2)   // As + 2xBs  = 110592
                   + 128 * 16 * (int)sizeof(float)        // fs         =   8192
                   + 64 * (int)sizeof(float);             // cs (padded)
    cudaFuncSetAttribute(fused_kernel, cudaFuncAttributeMaxDynamicSharedMemorySize, smem);

    fused_kernel<<<rows / 128, 512, smem>>>(x, W1, b1, rp, ryt, W2, b2, out);
}